// round 10
// baseline (speedup 1.0000x reference)
#include <cuda_runtime.h>

// out[i] = gen_map[x_gen[i]] + c * x_max_clock_speed[i] + d * x_max_tdp[i]
// N = 8388608. DRAM-bound at ~6.9 TB/s effective (3:1 R/W mix), ~86% of spec.
// This round: persistent grid-stride (148 SMs x 8 resident CTAs = 1184 blocks)
// to kill partial-wave tail (prev: 3.46 waves) and wave-transition cost.

#define BLOCK 256
#define GRID_PERSIST 1184   // 148 SMs * 8 CTAs/SM (256 thr, <=32 regs)

struct U64x4 { unsigned long long a, b, c, d; };

__device__ __forceinline__ U64x4 ldg_cg_256(const void* p) {
    U64x4 v;
    asm("ld.global.cg.v4.b64 {%0,%1,%2,%3}, [%4];"
        : "=l"(v.a), "=l"(v.b), "=l"(v.c), "=l"(v.d) : "l"(p));
    return v;
}
__device__ __forceinline__ void stg_cs_256(void* p, const U64x4& v) {
    asm volatile("st.global.cs.v4.b64 [%0], {%1,%2,%3,%4};"
        :: "l"(p), "l"(v.a), "l"(v.b), "l"(v.c), "l"(v.d) : "memory");
}

__device__ __forceinline__ unsigned lo32(unsigned long long x) { return (unsigned)x; }
__device__ __forceinline__ unsigned hi32(unsigned long long x) { return (unsigned)(x >> 32); }
__device__ __forceinline__ unsigned long long pack64(float lo, float hi) {
    return (unsigned long long)__float_as_uint(lo)
         | ((unsigned long long)__float_as_uint(hi) << 32);
}

// Persistent fast path: requires n % 8 == 0 (each unit = 8 elements).
__global__ void __launch_bounds__(BLOCK) fused_gather_axpy_persist(
    const int* __restrict__ x_gen,
    const float* __restrict__ cs,
    const float* __restrict__ tdp,
    const float* __restrict__ gen_map,
    const float* __restrict__ c_p,
    const float* __restrict__ d_p,
    float* __restrict__ out,
    int n8)   // number of 8-element units
{
    __shared__ float s_map[1024];
    ((float4*)s_map)[threadIdx.x] = __ldg(&((const float4*)gen_map)[threadIdx.x]);

    const float c = __ldg(c_p);
    const float d = __ldg(d_p);

    __syncthreads();

    const int stride = GRID_PERSIST * BLOCK;           // units per sweep
    for (int u = blockIdx.x * BLOCK + threadIdx.x; u < n8; u += stride) {
        const long long e = (long long)u * 8;

        // Front-batch 3 x 256-bit loads (96 B in flight per thread).
        U64x4 g = ldg_cg_256(x_gen + e);
        U64x4 s = ldg_cg_256(cs + e);
        U64x4 t = ldg_cg_256(tdp + e);

        float r0 = s_map[lo32(g.a)] + c * __uint_as_float(lo32(s.a)) + d * __uint_as_float(lo32(t.a));
        float r1 = s_map[hi32(g.a)] + c * __uint_as_float(hi32(s.a)) + d * __uint_as_float(hi32(t.a));
        float r2 = s_map[lo32(g.b)] + c * __uint_as_float(lo32(s.b)) + d * __uint_as_float(lo32(t.b));
        float r3 = s_map[hi32(g.b)] + c * __uint_as_float(hi32(s.b)) + d * __uint_as_float(hi32(t.b));
        float r4 = s_map[lo32(g.c)] + c * __uint_as_float(lo32(s.c)) + d * __uint_as_float(lo32(t.c));
        float r5 = s_map[hi32(g.c)] + c * __uint_as_float(hi32(s.c)) + d * __uint_as_float(hi32(t.c));
        float r6 = s_map[lo32(g.d)] + c * __uint_as_float(lo32(s.d)) + d * __uint_as_float(lo32(t.d));
        float r7 = s_map[hi32(g.d)] + c * __uint_as_float(hi32(s.d)) + d * __uint_as_float(hi32(t.d));

        U64x4 o;
        o.a = pack64(r0, r1);
        o.b = pack64(r2, r3);
        o.c = pack64(r4, r5);
        o.d = pack64(r6, r7);
        stg_cs_256(out + e, o);
    }
}

// Generic fallback (any N), element-granular.
__global__ void fused_gather_axpy_generic(
    const int* __restrict__ x_gen,
    const float* __restrict__ cs,
    const float* __restrict__ tdp,
    const float* __restrict__ gen_map,
    const float* __restrict__ c_p,
    const float* __restrict__ d_p,
    float* __restrict__ out,
    int n)
{
    int i = blockIdx.x * blockDim.x + threadIdx.x;
    if (i >= n) return;
    float c = __ldg(c_p);
    float d = __ldg(d_p);
    out[i] = __ldg(&gen_map[x_gen[i]]) + c * cs[i] + d * tdp[i];
}

extern "C" void kernel_launch(void* const* d_in, const int* in_sizes, int n_in,
                              void* d_out, int out_size)
{
    const int*   x_gen   = (const int*)d_in[0];
    // d_in[1] = x_ix (unused)
    const float* cs      = (const float*)d_in[2];
    const float* tdp     = (const float*)d_in[3];
    const float* gen_map = (const float*)d_in[4];
    // d_in[5] = b (unused)
    const float* c_p     = (const float*)d_in[6];
    const float* d_p     = (const float*)d_in[7];
    float* out = (float*)d_out;

    const int n = in_sizes[0];

    if (n % 8 == 0) {
        int n8 = n / 8;
        int grid = GRID_PERSIST;
        // If the problem is small, don't over-launch.
        int needed = (n8 + BLOCK - 1) / BLOCK;
        if (needed < grid) grid = needed;
        fused_gather_axpy_persist<<<grid, BLOCK>>>(
            x_gen, cs, tdp, gen_map, c_p, d_p, out, n8);
    } else {
        fused_gather_axpy_generic<<<(n + 255) / 256, 256>>>(
            x_gen, cs, tdp, gen_map, c_p, d_p, out, n);
    }
}

// round 11
// speedup vs baseline: 1.0890x; 1.0890x over previous
#include <cuda_runtime.h>

// out[i] = gen_map[x_gen[i]] + c * x_max_clock_speed[i] + d * x_max_tdp[i]
// N = 8388608. DRAM-bound: steady-state ~6.9 TB/s (~86% of spec) on a 3:1 R/W
// mixed stream. Converged structure: exact-cover grid (4096x256), smem gather
// table, 128-bit __ldcg streaming reads (best measured), 256-bit evict_first
// store to cut write-transaction count / bus turnarounds.

#define BLOCK 256
#define VPT 2  // float4 groups per thread -> 8 elems/thread

struct U64x4 { unsigned long long a, b, c, d; };

__device__ __forceinline__ void stg_ef_256(void* p, const U64x4& v) {
    asm volatile("st.global.L2::evict_first.v4.b64 [%0], {%1,%2,%3,%4};"
        :: "l"(p), "l"(v.a), "l"(v.b), "l"(v.c), "l"(v.d) : "memory");
}
__device__ __forceinline__ unsigned long long pack64(float lo, float hi) {
    return (unsigned long long)__float_as_uint(lo)
         | ((unsigned long long)__float_as_uint(hi) << 32);
}

// Fast path: NO bounds checks; grid exactly covers n4 float4-units.
// Thread handles float4-units {base, base+BLOCK} -> 8 consecutive-by-128b elems,
// and the two units are 1024 floats apart; store fuses them? No — store must be
// contiguous. Layout: unit0 = base, unit1 = base + 1 (adjacent), so the two
// float4 results form one contiguous 32-byte store.
__global__ void __launch_bounds__(BLOCK) fused_gather_axpy_v6(
    const int4* __restrict__ x_gen4,
    const float4* __restrict__ cs4,
    const float4* __restrict__ tdp4,
    const float* __restrict__ gen_map,
    const float* __restrict__ c_p,
    const float* __restrict__ d_p,
    float* __restrict__ out)
{
    __shared__ float s_map[1024];
    ((float4*)s_map)[threadIdx.x] = __ldg(&((const float4*)gen_map)[threadIdx.x]);

    const float c = __ldg(c_p);
    const float d = __ldg(d_p);

    // Each thread owns two ADJACENT float4 units so its 8 results are one
    // contiguous 32 B region -> single 256-bit store.
    const int base = (blockIdx.x * BLOCK + threadIdx.x) * VPT;

    // Front-batch all 6 128-bit streaming loads (MLP = 6).
    int4   g0 = __ldcg(&x_gen4[base]);
    int4   g1 = __ldcg(&x_gen4[base + 1]);
    float4 s0 = __ldcg(&cs4[base]);
    float4 s1 = __ldcg(&cs4[base + 1]);
    float4 t0 = __ldcg(&tdp4[base]);
    float4 t1 = __ldcg(&tdp4[base + 1]);

    __syncthreads();

    float r0 = s_map[g0.x] + c * s0.x + d * t0.x;
    float r1 = s_map[g0.y] + c * s0.y + d * t0.y;
    float r2 = s_map[g0.z] + c * s0.z + d * t0.z;
    float r3 = s_map[g0.w] + c * s0.w + d * t0.w;
    float r4 = s_map[g1.x] + c * s1.x + d * t1.x;
    float r5 = s_map[g1.y] + c * s1.y + d * t1.y;
    float r6 = s_map[g1.z] + c * s1.z + d * t1.z;
    float r7 = s_map[g1.w] + c * s1.w + d * t1.w;

    U64x4 o;
    o.a = pack64(r0, r1);
    o.b = pack64(r2, r3);
    o.c = pack64(r4, r5);
    o.d = pack64(r6, r7);
    stg_ef_256(out + (long long)base * 4, o);
}

// Generic fallback (any N), element-granular.
__global__ void fused_gather_axpy_generic(
    const int* __restrict__ x_gen,
    const float* __restrict__ cs,
    const float* __restrict__ tdp,
    const float* __restrict__ gen_map,
    const float* __restrict__ c_p,
    const float* __restrict__ d_p,
    float* __restrict__ out,
    int n)
{
    int i = blockIdx.x * blockDim.x + threadIdx.x;
    if (i >= n) return;
    float c = __ldg(c_p);
    float d = __ldg(d_p);
    out[i] = __ldg(&gen_map[x_gen[i]]) + c * cs[i] + d * tdp[i];
}

extern "C" void kernel_launch(void* const* d_in, const int* in_sizes, int n_in,
                              void* d_out, int out_size)
{
    const int*   x_gen   = (const int*)d_in[0];
    // d_in[1] = x_ix (unused)
    const float* cs      = (const float*)d_in[2];
    const float* tdp     = (const float*)d_in[3];
    const float* gen_map = (const float*)d_in[4];
    // d_in[5] = b (unused)
    const float* c_p     = (const float*)d_in[6];
    const float* d_p     = (const float*)d_in[7];
    float* out = (float*)d_out;

    const int n  = in_sizes[0];
    const int n4 = n / 4;
    const int units_per_block = BLOCK * VPT;

    if ((n % 4 == 0) && (n4 % units_per_block == 0)) {
        // Exact-cover fast path (holds for N = 8388608: 4096 blocks).
        fused_gather_axpy_v6<<<n4 / units_per_block, BLOCK>>>(
            (const int4*)x_gen, (const float4*)cs, (const float4*)tdp,
            gen_map, c_p, d_p, out);
    } else {
        fused_gather_axpy_generic<<<(n + 255) / 256, 256>>>(
            x_gen, cs, tdp, gen_map, c_p, d_p, out, n);
    }
}